// round 3
// baseline (speedup 1.0000x reference)
#include <cuda_runtime.h>

// Gaussian 15x15 separable blur, 8192x8192 fp32, reflect padding, stride 1.
// Fused single-pass: raw tile -> smem -> horizontal (f32x2 packed) -> smem
// -> vertical (f32x2 packed) -> global.

#define IMG_W 8192
#define IMG_H 8192
#define KS 15
#define HALO 7
#define TW 128
#define TH 64
#define RAW_W (TW + 2*HALO)        // 142
#define RAW_ROWS (TH + 2*HALO)     // 78
#define RAW_PITCH 143              // odd -> conflict-free row-strided LDS
#define INT_PITCH 130              // even (float2 aligned), 2-way STS conflict only
#define SMEM_BYTES ((RAW_ROWS*RAW_PITCH + RAW_ROWS*INT_PITCH) * 4)  // 85176

static __device__ float g_kx[KS];
static __device__ float g_ky[KS];

__device__ __forceinline__ int reflect_idx(int p, int n) {
    p = (p < 0) ? -p : p;
    p = (p >= n) ? (2*n - 2 - p) : p;
    return p;
}

__device__ __forceinline__ unsigned long long pk2(float lo, float hi) {
    unsigned long long r;
    asm("mov.b64 %0, {%1, %2};" : "=l"(r) : "f"(lo), "f"(hi));
    return r;
}
__device__ __forceinline__ void upk2(unsigned long long v, float& lo, float& hi) {
    asm("mov.b64 {%0, %1}, %2;" : "=f"(lo), "=f"(hi) : "l"(v));
}
// packed dual-FMA: two fp32 FMAs per fma-pipe issue (sm_103a FFMA2)
__device__ __forceinline__ unsigned long long ffma2(unsigned long long a,
                                                    unsigned long long b,
                                                    unsigned long long c) {
    unsigned long long d;
    asm("fma.rn.f32x2 %0, %1, %2, %3;" : "=l"(d) : "l"(a), "l"(b), "l"(c));
    return d;
}

// Recover separable 1D kernels from the 2D kernel (outer product, rows/cols sum to 1):
// column sums -> kx, row sums -> ky.
__global__ void prep_kernel(const float* __restrict__ k2d) {
    int t = threadIdx.x;
    if (t < KS) {
        float sx = 0.f, sy = 0.f;
#pragma unroll
        for (int i = 0; i < KS; i++) {
            sx += k2d[i * KS + t];
            sy += k2d[t * KS + i];
        }
        g_kx[t] = sx;
        g_ky[t] = sy;
    }
}

extern __shared__ float smem[];

__global__ void __launch_bounds__(256)
gauss_kernel(const float* __restrict__ in, float* __restrict__ out) {
    float* sRaw = smem;                                   // RAW_ROWS x RAW_PITCH
    float* sInt = smem + RAW_ROWS * RAW_PITCH;            // RAW_ROWS x INT_PITCH

    const int tid  = threadIdx.x;
    const int lane = tid & 31;
    const int wrp  = tid >> 5;                            // 0..7
    const int x0 = blockIdx.x * TW;
    const int y0 = blockIdx.y * TH;

    // ---- stage 1: load raw tile (reflect-padded) -> smem, coalesced ----
#pragma unroll 1
    for (int r = wrp; r < RAW_ROWS; r += 8) {
        const int gy = reflect_idx(y0 - HALO + r, IMG_H);
        const float* rowp = in + (long)gy * IMG_W;
        float* srow = sRaw + r * RAW_PITCH;
#pragma unroll 1
        for (int c = lane; c < RAW_W; c += 32) {
            int gx = reflect_idx(x0 - HALO + c, IMG_W);
            srow[c] = __ldg(rowp + gx);
        }
    }
    __syncthreads();

    // ---- stage 2: horizontal pass (packed f32x2, sliding window) ----
    // warp = 32 consecutive rows (pitch 143 -> 32 distinct banks), 8 output cols/thread
    {
        unsigned long long cx2[KS];
#pragma unroll
        for (int k = 0; k < KS; k++) { float c = g_kx[k]; cx2[k] = pk2(c, c); }

#pragma unroll 1
        for (int gi = wrp; gi < 16; gi += 8) {
            const int cbase = gi * 8;
#pragma unroll 1
            for (int rb = 0; rb < 3; rb++) {
                const int r = rb * 32 + lane;
                if (r < RAW_ROWS) {
                    const float* srow = sRaw + r * RAW_PITCH + cbase;
                    unsigned long long acc[4];
#pragma unroll
                    for (int m = 0; m < 4; m++) acc[m] = 0ull;
                    float vj = srow[0];
#pragma unroll
                    for (int j = 0; j < 21; j++) {
                        float vn = srow[j + 1];
                        unsigned long long pr = pk2(vj, vn);
#pragma unroll
                        for (int m = 0; m < 4; m++) {
                            int k = j - 2 * m;
                            if (k >= 0 && k < KS) acc[m] = ffma2(cx2[k], pr, acc[m]);
                        }
                        vj = vn;
                    }
                    float2* drow = (float2*)(sInt + r * INT_PITCH + cbase);
#pragma unroll
                    for (int m = 0; m < 4; m++) {
                        float lo, hi; upk2(acc[m], lo, hi);
                        drow[m] = make_float2(lo, hi);
                    }
                }
            }
        }
    }
    __syncthreads();

    // ---- stage 3: vertical pass (packed f32x2 over natural column pairs) ----
    // thread -> (column-pair p, 16-row chunk q); warp reads 64 consecutive floats
    {
        unsigned long long cy2[KS];
#pragma unroll
        for (int k = 0; k < KS; k++) { float c = g_ky[k]; cy2[k] = pk2(c, c); }

        const int p = tid & 63;       // 0..63 column pairs
        const int q = tid >> 6;       // 0..3 row chunks
        const int rbase = q * 16;

        unsigned long long acc[16];
#pragma unroll
        for (int m = 0; m < 16; m++) acc[m] = 0ull;

        const float* colp = sInt + rbase * INT_PITCH + 2 * p;
#pragma unroll
        for (int j = 0; j < 30; j++) {
            float2 v2 = *(const float2*)(colp + (long)j * INT_PITCH);
            unsigned long long v = pk2(v2.x, v2.y);
#pragma unroll
            for (int m = 0; m < 16; m++) {
                int k = j - m;
                if (k >= 0 && k < KS) acc[m] = ffma2(cy2[k], v, acc[m]);
            }
        }

        float* obase = out + (long)(y0 + rbase) * IMG_W + x0 + 2 * p;
#pragma unroll
        for (int m = 0; m < 16; m++) {
            float lo, hi; upk2(acc[m], lo, hi);
            *(float2*)(obase + (long)m * IMG_W) = make_float2(lo, hi);
        }
    }
}

extern "C" void kernel_launch(void* const* d_in, const int* in_sizes, int n_in,
                              void* d_out, int out_size) {
    const float* img = (const float*)d_in[0];   // [8192,8192] f32
    const float* ker = (const float*)d_in[1];   // [15,15] f32
    float* out = (float*)d_out;                 // [8192,8192] f32

    (void)in_sizes; (void)n_in; (void)out_size;

    cudaFuncSetAttribute(gauss_kernel,
                         cudaFuncAttributeMaxDynamicSharedMemorySize, SMEM_BYTES);

    prep_kernel<<<1, 32>>>(ker);

    dim3 grid(IMG_W / TW, IMG_H / TH);   // 64 x 128
    gauss_kernel<<<grid, 256, SMEM_BYTES>>>(img, out);
}

// round 4
// speedup vs baseline: 2.0105x; 2.0105x over previous
#include <cuda_runtime.h>

// Gaussian 15x15 separable blur, 8192x8192 fp32, reflect pad, stride 1.
// Scanline-streaming fused kernel:
//   - CTA = 128 threads, strip of 256 columns x 64 output rows
//   - raw rows stream through a 32-row smem ring, prefetched 15 rows ahead (float4)
//   - horizontal conv: per-thread 2 cols, packed f32x2, symmetric coeffs
//   - vertical conv: 15-slot f32x2 register accumulator ring (no smem intermediate)

#define IMG_W 8192
#define IMG_H 8192
#define KS 15
#define HALO 7
#define TPB 128
#define TILE_W 256
#define TILE_H 64
#define NROWS (TILE_H + 2*HALO)     // 78 input rows per strip
#define ROW_F (TILE_W + 16)         // 272 floats per buffered row
#define RING 32
#define SMEM_BYTES (RING * ROW_F * 4)   // 34816 B

typedef unsigned long long ull;

static __device__ float g_kx[KS];
static __device__ float g_ky[KS];

__device__ __forceinline__ int reflect_idx(int p, int n) {
    p = (p < 0) ? -p : p;
    p = (p >= n) ? (2*n - 2 - p) : p;
    return p;
}

__device__ __forceinline__ ull pk2(float lo, float hi) {
    ull r; asm("mov.b64 %0, {%1, %2};" : "=l"(r) : "f"(lo), "f"(hi)); return r;
}
__device__ __forceinline__ void upk2(ull v, float& lo, float& hi) {
    asm("mov.b64 {%0, %1}, %2;" : "=f"(lo), "=f"(hi) : "l"(v));
}
__device__ __forceinline__ ull ffma2(ull a, ull b, ull c) {
    ull d; asm("fma.rn.f32x2 %0, %1, %2, %3;" : "=l"(d) : "l"(a), "l"(b), "l"(c)); return d;
}
__device__ __forceinline__ ull add2(ull a, ull b) {
    ull d; asm("add.rn.f32x2 %0, %1, %2;" : "=l"(d) : "l"(a), "l"(b)); return d;
}

// Recover separable 1D kernels from the outer-product 2D kernel (rows/cols sum to 1).
__global__ void prep_kernel(const float* __restrict__ k2d) {
    int t = threadIdx.x;
    if (t < KS) {
        float sx = 0.f, sy = 0.f;
#pragma unroll
        for (int i = 0; i < KS; i++) { sx += k2d[i * KS + t]; sy += k2d[t * KS + i]; }
        g_kx[t] = sx;
        g_ky[t] = sy;
    }
}

// One input row: horizontal conv for this thread's 2 columns, feed vertical ring.
// RMOD = r mod 15 (compile-time), DMAX = min(r, 14).
template<int RMOD, int DMAX>
__device__ __forceinline__ void row_step(const float* rowbuf, int p,
                                         ull* acc, const ull* kx2, const ull* ky2) {
    const ull* w = reinterpret_cast<const ull*>(rowbuf) + p;   // aligned f32 pairs
    ull P[9]; float lo[9], hi[9];
#pragma unroll
    for (int c = 0; c < 9; c++) { P[c] = w[c]; upk2(P[c], lo[c], hi[c]); }
    // T_j = (raw[2p+1+j], raw[2p+2+j]), j = 0..14
    ull T[15];
#pragma unroll
    for (int i = 0; i < 8; i++) T[2*i] = pk2(hi[i], lo[i+1]);
#pragma unroll
    for (int i = 0; i < 7; i++) T[2*i+1] = P[i+1];
    // symmetric horizontal: h = kx[7]*T7 + sum_j kx[j]*(T_j + T_{14-j})
    ull h = ffma2(kx2[7], T[7], 0ull);
#pragma unroll
    for (int j = 0; j < 7; j++) h = ffma2(kx2[j], add2(T[j], T[14 - j]), h);
    // vertical: h_r contributes to outputs t = r-14..r with coeff ky[r-t]
#pragma unroll
    for (int d = 0; d <= DMAX; d++) {
        const int s = ((RMOD - d) % 15 + 15) % 15;
        const int ci = (d < 8) ? d : 14 - d;
        acc[s] = ffma2(ky2[ci], h, acc[s]);
    }
}

// Prefetch 15 raw rows (base..base+14) into the smem ring (clipped to NROWS).
__device__ __forceinline__ void prefetch_rows(float* ring_, const float* in,
                                              int x0, int y0, int base,
                                              bool xb, int tid) {
#pragma unroll
    for (int rr = 0; rr < 15; rr++) {
        int r = base + rr;
        if (r < NROWS) {
            int gy = reflect_idx(y0 - HALO + r, IMG_H);
            const float* row = in + (size_t)gy * IMG_W;
            float* dst = ring_ + (r & (RING - 1)) * ROW_F;
            if (!xb) {
                if (tid < ROW_F / 4)
                    ((float4*)dst)[tid] = __ldg((const float4*)(row + x0 - 8) + tid);
            } else {
                for (int i = tid; i < ROW_F; i += TPB)
                    dst[i] = __ldg(row + reflect_idx(x0 - 8 + i, IMG_W));
            }
        }
    }
}

extern __shared__ float ring[];

__global__ void __launch_bounds__(TPB)
gauss_kernel(const float* __restrict__ in, float* __restrict__ out) {
    const int tid = threadIdx.x;
    const int p = tid;                              // column-pair index 0..127
    const int x0 = blockIdx.x * TILE_W;
    const int y0 = blockIdx.y * TILE_H;
    const bool xb = (blockIdx.x == 0) || (blockIdx.x == gridDim.x - 1);

    ull kx2[8], ky2[8];
#pragma unroll
    for (int i = 0; i < 8; i++) {
        float a = g_kx[i]; kx2[i] = pk2(a, a);
        float b = g_ky[i]; ky2[i] = pk2(b, b);
    }
    ull acc[15];
#pragma unroll
    for (int i = 0; i < 15; i++) acc[i] = 0ull;

    prefetch_rows(ring, in, x0, y0, 0, xb, tid);    // rows 0..14
    __syncthreads();
    prefetch_rows(ring, in, x0, y0, 15, xb, tid);   // rows 15..29 (in flight)

#define ROWBUF(R) (ring + ((R) & (RING - 1)) * ROW_F)
    // warmup: r = 0..13 (partial vertical adds)
    row_step< 0, 0>(ROWBUF( 0), p, acc, kx2, ky2);
    row_step< 1, 1>(ROWBUF( 1), p, acc, kx2, ky2);
    row_step< 2, 2>(ROWBUF( 2), p, acc, kx2, ky2);
    row_step< 3, 3>(ROWBUF( 3), p, acc, kx2, ky2);
    row_step< 4, 4>(ROWBUF( 4), p, acc, kx2, ky2);
    row_step< 5, 5>(ROWBUF( 5), p, acc, kx2, ky2);
    row_step< 6, 6>(ROWBUF( 6), p, acc, kx2, ky2);
    row_step< 7, 7>(ROWBUF( 7), p, acc, kx2, ky2);
    row_step< 8, 8>(ROWBUF( 8), p, acc, kx2, ky2);
    row_step< 9, 9>(ROWBUF( 9), p, acc, kx2, ky2);
    row_step<10,10>(ROWBUF(10), p, acc, kx2, ky2);
    row_step<11,11>(ROWBUF(11), p, acc, kx2, ky2);
    row_step<12,12>(ROWBUF(12), p, acc, kx2, ky2);
    row_step<13,13>(ROWBUF(13), p, acc, kx2, ky2);
    __syncthreads();

    float* obase = out + (size_t)y0 * IMG_W + x0 + 2 * p;

    // main: 4 blocks of 15 rows (r = 14..73 -> outputs t = 0..59)
#pragma unroll 1
    for (int rb = 0; rb < 4; rb++) {
        prefetch_rows(ring, in, x0, y0, 30 + 15 * rb, xb, tid);
        const int rbase = 14 + 15 * rb;
        float* op = obase + (size_t)(15 * rb) * IMG_W;
#define MAINB(U) { \
        row_step<(14 + (U)) % 15, 14>(ring + ((rbase + (U)) & (RING - 1)) * ROW_F, \
                                      p, acc, kx2, ky2); \
        { constexpr int S = ((14 + (U)) % 15 + 1) % 15; \
          float l_, h_; upk2(acc[S], l_, h_); \
          *(float2*)(op + (size_t)(U) * IMG_W) = make_float2(l_, h_); \
          acc[S] = 0ull; } }
        MAINB(0)  MAINB(1)  MAINB(2)  MAINB(3)  MAINB(4)
        MAINB(5)  MAINB(6)  MAINB(7)  MAINB(8)  MAINB(9)
        MAINB(10) MAINB(11) MAINB(12) MAINB(13) MAINB(14)
        __syncthreads();
    }

    // tail: r = 74..77 -> outputs t = 60..63
#define TAILB(R) { \
        row_step<(R) % 15, 14>(ROWBUF(R), p, acc, kx2, ky2); \
        constexpr int S = ((R) % 15 + 1) % 15; \
        float l_, h_; upk2(acc[S], l_, h_); \
        *(float2*)(obase + (size_t)((R) - 14) * IMG_W) = make_float2(l_, h_); \
        acc[S] = 0ull; }
    TAILB(74) TAILB(75) TAILB(76) TAILB(77)
}

extern "C" void kernel_launch(void* const* d_in, const int* in_sizes, int n_in,
                              void* d_out, int out_size) {
    const float* img = (const float*)d_in[0];   // [8192,8192] f32
    const float* ker = (const float*)d_in[1];   // [15,15] f32
    float* out = (float*)d_out;                 // [8192,8192] f32
    (void)in_sizes; (void)n_in; (void)out_size;

    prep_kernel<<<1, 32>>>(ker);

    dim3 grid(IMG_W / TILE_W, IMG_H / TILE_H);  // 32 x 128
    gauss_kernel<<<grid, TPB, SMEM_BYTES>>>(img, out);
}

// round 5
// speedup vs baseline: 3.1368x; 1.5602x over previous
#include <cuda_runtime.h>
#include <cstdint>

// Gaussian 15x15 separable blur, 8192x8192 fp32, reflect pad, stride 1.
// Scanline streaming: cp.async row prefetch into a 32-row smem ring,
// horizontal conv (packed f32x2, tree-reduced), vertical conv via a
// 15-slot f32x2 register accumulator ring. No intermediate smem pass.

#define IMG_W 8192
#define IMG_H 8192
#define KS 15
#define HALO 7
#define TPB 128
#define TILE_W 256
#define TILE_H 64
#define NROWS (TILE_H + 2*HALO)     // 78 input rows per strip
#define ROW_F (TILE_W + 16)         // 272 floats per buffered row
#define ROW_V4 (ROW_F / 4)          // 68 float4 per row
#define RING 32
#define SMEM_BYTES (RING * ROW_F * 4)   // 34816 B

typedef unsigned long long ull;

static __device__ float g_kx[KS];
static __device__ float g_ky[KS];

__device__ __forceinline__ int reflect_idx(int p, int n) {
    p = (p < 0) ? -p : p;
    p = (p >= n) ? (2*n - 2 - p) : p;
    return p;
}

__device__ __forceinline__ ull pk2(float lo, float hi) {
    ull r; asm("mov.b64 %0, {%1, %2};" : "=l"(r) : "f"(lo), "f"(hi)); return r;
}
__device__ __forceinline__ void upk2(ull v, float& lo, float& hi) {
    asm("mov.b64 {%0, %1}, %2;" : "=f"(lo), "=f"(hi) : "l"(v));
}
__device__ __forceinline__ ull ffma2(ull a, ull b, ull c) {
    ull d; asm("fma.rn.f32x2 %0, %1, %2, %3;" : "=l"(d) : "l"(a), "l"(b), "l"(c)); return d;
}
__device__ __forceinline__ ull add2(ull a, ull b) {
    ull d; asm("add.rn.f32x2 %0, %1, %2;" : "=l"(d) : "l"(a), "l"(b)); return d;
}
__device__ __forceinline__ ull mul2(ull a, ull b) {
    ull d; asm("mul.rn.f32x2 %0, %1, %2;" : "=l"(d) : "l"(a), "l"(b)); return d;
}

__device__ __forceinline__ void cp16(uint32_t saddr, const float* g) {
    asm volatile("cp.async.cg.shared.global [%0], [%1], 16;"
                 :: "r"(saddr), "l"(g) : "memory");
}
#define CP_COMMIT() asm volatile("cp.async.commit_group;" ::: "memory")
#define CP_WAIT(N)  asm volatile("cp.async.wait_group %0;" :: "n"(N) : "memory")

// Recover separable 1D kernels from the outer-product 2D kernel (rows/cols sum to 1).
__global__ void prep_kernel(const float* __restrict__ k2d) {
    int t = threadIdx.x;
    if (t < KS) {
        float sx = 0.f, sy = 0.f;
#pragma unroll
        for (int i = 0; i < KS; i++) { sx += k2d[i * KS + t]; sy += k2d[t * KS + i]; }
        g_kx[t] = sx;
        g_ky[t] = sy;
    }
}

// One input row: horizontal conv for this thread's 2 columns, feed vertical ring.
// RMOD = r mod 15 (compile-time), DMAX = min(r, 14).
template<int RMOD, int DMAX>
__device__ __forceinline__ void row_step(const float* rowbuf, int p,
                                         ull* acc, const ull* kx2, const ull* ky2) {
    const ull* w = reinterpret_cast<const ull*>(rowbuf) + p;   // aligned f32 pairs
    ull P[9]; float lo[9], hi[9];
#pragma unroll
    for (int c = 0; c < 9; c++) { P[c] = w[c]; upk2(P[c], lo[c], hi[c]); }
    // T_j = (raw[2p+1+j], raw[2p+2+j]), j = 0..14
    ull T[15];
#pragma unroll
    for (int i = 0; i < 8; i++) T[2*i] = pk2(hi[i], lo[i+1]);
#pragma unroll
    for (int i = 0; i < 7; i++) T[2*i+1] = P[i+1];
    // symmetric pairs, then 4 independent chains + add tree (shallow deps)
    ull u0 = add2(T[0], T[14]);
    ull u1 = add2(T[1], T[13]);
    ull u2 = add2(T[2], T[12]);
    ull u3 = add2(T[3], T[11]);
    ull u4 = add2(T[4], T[10]);
    ull u5 = add2(T[5], T[9]);
    ull u6 = add2(T[6], T[8]);
    ull a0 = ffma2(kx2[4], u4, mul2(kx2[0], u0));
    ull a1 = ffma2(kx2[5], u5, mul2(kx2[1], u1));
    ull a2 = ffma2(kx2[6], u6, mul2(kx2[2], u2));
    ull a3 = ffma2(kx2[7], T[7], mul2(kx2[3], u3));
    ull h = add2(add2(a0, a1), add2(a2, a3));
    // vertical: h_r contributes to outputs t = r-14..r with coeff ky[r-t]
#pragma unroll
    for (int d = 0; d <= DMAX; d++) {
        const int s = ((RMOD - d) % 15 + 15) % 15;
        const int ci = (d < 8) ? d : 14 - d;
        acc[s] = ffma2(ky2[ci], h, acc[s]);
    }
}

// Issue async prefetch of rows [base, base+15) into the ring (clipped to NROWS).
__device__ __forceinline__ void prefetch_rows(uint32_t ring_s, float* ring_g,
                                              const float* in,
                                              int x0, int y0, int base,
                                              bool xb, int tid) {
    if (!xb) {
        // 15 rows x 68 float4 flattened over all threads (8 cp.asyncs each)
#pragma unroll 1
        for (int idx = tid; idx < 15 * ROW_V4; idx += TPB) {
            int rr = idx / ROW_V4;
            int cc = idx - rr * ROW_V4;
            int r = base + rr;
            if (r < NROWS) {
                int gy = reflect_idx(y0 - HALO + r, IMG_H);
                const float* src = in + (size_t)gy * IMG_W + (x0 - 8 + 4 * cc);
                uint32_t dst = ring_s + (uint32_t)(((r & (RING - 1)) * ROW_F + 4 * cc) * 4);
                cp16(dst, src);
            }
        }
    } else {
        // boundary strips: per-element reflect (2 of 32 strips)
#pragma unroll 1
        for (int rr = 0; rr < 15; rr++) {
            int r = base + rr;
            if (r < NROWS) {
                int gy = reflect_idx(y0 - HALO + r, IMG_H);
                const float* row = in + (size_t)gy * IMG_W;
                float* dst = ring_g + (r & (RING - 1)) * ROW_F;
                for (int i = tid; i < ROW_F; i += TPB)
                    dst[i] = __ldg(row + reflect_idx(x0 - 8 + i, IMG_W));
            }
        }
    }
}

extern __shared__ float ring[];

__global__ void __launch_bounds__(TPB, 6)
gauss_kernel(const float* __restrict__ in, float* __restrict__ out) {
    const int tid = threadIdx.x;
    const int p = tid;                              // column-pair index 0..127
    const int x0 = blockIdx.x * TILE_W;
    const int y0 = blockIdx.y * TILE_H;
    const bool xb = (blockIdx.x == 0) || (blockIdx.x == gridDim.x - 1);
    const uint32_t ring_s = (uint32_t)__cvta_generic_to_shared(ring);

    ull kx2[8], ky2[8];
#pragma unroll
    for (int i = 0; i < 8; i++) {
        float a = g_kx[i]; kx2[i] = pk2(a, a);
        float b = g_ky[i]; ky2[i] = pk2(b, b);
    }
    ull acc[15];
#pragma unroll
    for (int i = 0; i < 15; i++) acc[i] = 0ull;

    prefetch_rows(ring_s, ring, in, x0, y0, 0, xb, tid);  CP_COMMIT();   // g0: rows 0..14
    prefetch_rows(ring_s, ring, in, x0, y0, 15, xb, tid); CP_COMMIT();   // g1: rows 15..29
    CP_WAIT(1);               // g0 complete
    __syncthreads();

#define ROWBUF(R) (ring + ((R) & (RING - 1)) * ROW_F)
    // warmup: r = 0..13 (partial vertical adds)
    row_step< 0, 0>(ROWBUF( 0), p, acc, kx2, ky2);
    row_step< 1, 1>(ROWBUF( 1), p, acc, kx2, ky2);
    row_step< 2, 2>(ROWBUF( 2), p, acc, kx2, ky2);
    row_step< 3, 3>(ROWBUF( 3), p, acc, kx2, ky2);
    row_step< 4, 4>(ROWBUF( 4), p, acc, kx2, ky2);
    row_step< 5, 5>(ROWBUF( 5), p, acc, kx2, ky2);
    row_step< 6, 6>(ROWBUF( 6), p, acc, kx2, ky2);
    row_step< 7, 7>(ROWBUF( 7), p, acc, kx2, ky2);
    row_step< 8, 8>(ROWBUF( 8), p, acc, kx2, ky2);
    row_step< 9, 9>(ROWBUF( 9), p, acc, kx2, ky2);
    row_step<10,10>(ROWBUF(10), p, acc, kx2, ky2);
    row_step<11,11>(ROWBUF(11), p, acc, kx2, ky2);
    row_step<12,12>(ROWBUF(12), p, acc, kx2, ky2);
    row_step<13,13>(ROWBUF(13), p, acc, kx2, ky2);
    __syncthreads();   // all warmup reads done before ring slots 0..12 are rewritten

    float* obase = out + (size_t)y0 * IMG_W + x0 + 2 * p;

    // main: 4 blocks of 15 rows (r = 14..73 -> outputs t = 0..59)
#pragma unroll 1
    for (int rb = 0; rb < 4; rb++) {
        prefetch_rows(ring_s, ring, in, x0, y0, 30 + 15 * rb, xb, tid);
        CP_COMMIT();          // g(rb+2)
        CP_WAIT(1);           // g(rb+1) complete -> rows 15+15rb..29+15rb ready
        __syncthreads();
        const int rbase = 14 + 15 * rb;
        float* op = obase + (size_t)(15 * rb) * IMG_W;
#define MAINB(U) { \
        row_step<(14 + (U)) % 15, 14>(ring + ((rbase + (U)) & (RING - 1)) * ROW_F, \
                                      p, acc, kx2, ky2); \
        { constexpr int S = ((14 + (U)) % 15 + 1) % 15; \
          float l_, h_; upk2(acc[S], l_, h_); \
          *(float2*)(op + (size_t)(U) * IMG_W) = make_float2(l_, h_); \
          acc[S] = 0ull; } }
        MAINB(0)  MAINB(1)  MAINB(2)  MAINB(3)  MAINB(4)
        MAINB(5)  MAINB(6)  MAINB(7)  MAINB(8)  MAINB(9)
        MAINB(10) MAINB(11) MAINB(12) MAINB(13) MAINB(14)
        __syncthreads();      // reads done before next block overwrites slots
    }

    // tail: r = 74..77 -> outputs t = 60..63
    CP_WAIT(0);               // last group (rows 75..77) complete
    __syncthreads();
#define TAILB(R) { \
        row_step<(R) % 15, 14>(ROWBUF(R), p, acc, kx2, ky2); \
        constexpr int S = ((R) % 15 + 1) % 15; \
        float l_, h_; upk2(acc[S], l_, h_); \
        *(float2*)(obase + (size_t)((R) - 14) * IMG_W) = make_float2(l_, h_); \
        acc[S] = 0ull; }
    TAILB(74) TAILB(75) TAILB(76) TAILB(77)
}

extern "C" void kernel_launch(void* const* d_in, const int* in_sizes, int n_in,
                              void* d_out, int out_size) {
    const float* img = (const float*)d_in[0];   // [8192,8192] f32
    const float* ker = (const float*)d_in[1];   // [15,15] f32
    float* out = (float*)d_out;                 // [8192,8192] f32
    (void)in_sizes; (void)n_in; (void)out_size;

    prep_kernel<<<1, 32>>>(ker);

    dim3 grid(IMG_W / TILE_W, IMG_H / TILE_H);  // 32 x 128
    gauss_kernel<<<grid, TPB, SMEM_BYTES>>>(img, out);
}